// round 6
// baseline (speedup 1.0000x reference)
#include <cuda_runtime.h>
#include <cuda_bf16.h>
#include <math.h>

// Problem shapes (fixed by the reference)
#define N1 4096
#define N2 8192
#define D  256
#define ALPHA 0.2f

#define MAXR 256     // max nonzeros per adj row (mean ~83)
#define MAXC 4352    // max nonzeros per adj column (col 0 has 4096, others ~41)

// ---------------- scratch (device globals: allocation-free) ----------------
__device__ float g_x4att[(size_t)N2 * D];    // 8 MB
__device__ float g_edge [(size_t)N1 * D];    // 4 MB
__device__ float g_edge4[(size_t)N1 * D];    // 4 MB
__device__ float g_adjT [(size_t)N2 * N1];   // 128 MB
__device__ float g_sn[N2];
__device__ float g_se[N1];
__device__ int   g_rowcnt[N1];
__device__ int   g_colcnt[N2];
__device__ int   g_rowidx[(size_t)N1 * MAXR];   // 4 MB
__device__ int   g_colidx[(size_t)N2 * MAXC];   // ~143 MB

// ---------------- SGEMM: C[M,256] = A[M,256] @ B[256,256] ------------------
// 64x64 tile, BK=16, 256 threads, 4x4 register microtile.
__global__ __launch_bounds__(256) void sgemm256(
    const float* __restrict__ A, const float* __restrict__ B,
    float* __restrict__ C)
{
    __shared__ __align__(16) float As[16][68];  // transposed, padded (stride 272B, 16B-aligned rows)
    __shared__ __align__(16) float Bs[16][64];

    int tid  = threadIdx.x;
    int tx   = tid & 15;
    int ty   = tid >> 4;
    int row0 = blockIdx.y * 64;
    int col0 = blockIdx.x * 64;

    int arow = tid >> 2;          // 0..63
    int akq  = (tid & 3) << 2;    // 0,4,8,12
    int brow = tid >> 4;          // 0..15
    int bcol = (tid & 15) << 2;   // 0..60

    float acc[4][4];
    #pragma unroll
    for (int r = 0; r < 4; r++)
        #pragma unroll
        for (int c = 0; c < 4; c++) acc[r][c] = 0.0f;

    for (int kb = 0; kb < 256; kb += 16) {
        float4 av = *(const float4*)(A + (size_t)(row0 + arow) * 256 + kb + akq);
        As[akq + 0][arow] = av.x;
        As[akq + 1][arow] = av.y;
        As[akq + 2][arow] = av.z;
        As[akq + 3][arow] = av.w;
        *(float4*)(&Bs[brow][bcol]) =
            *(const float4*)(B + (size_t)(kb + brow) * 256 + col0 + bcol);
        __syncthreads();

        #pragma unroll
        for (int kk = 0; kk < 16; kk++) {
            float4 a = *(const float4*)(&As[kk][ty << 2]);
            float4 b = *(const float4*)(&Bs[kk][tx << 2]);
            acc[0][0] += a.x * b.x; acc[0][1] += a.x * b.y; acc[0][2] += a.x * b.z; acc[0][3] += a.x * b.w;
            acc[1][0] += a.y * b.x; acc[1][1] += a.y * b.y; acc[1][2] += a.y * b.z; acc[1][3] += a.y * b.w;
            acc[2][0] += a.z * b.x; acc[2][1] += a.z * b.y; acc[2][2] += a.z * b.z; acc[2][3] += a.z * b.w;
            acc[3][0] += a.w * b.x; acc[3][1] += a.w * b.y; acc[3][2] += a.w * b.z; acc[3][3] += a.w * b.w;
        }
        __syncthreads();
    }

    #pragma unroll
    for (int r = 0; r < 4; r++) {
        float4 vv = make_float4(acc[r][0], acc[r][1], acc[r][2], acc[r][3]);
        *(float4*)(C + (size_t)(row0 + (ty << 2) + r) * 256 + col0 + (tx << 2)) = vv;
    }
}

// ---------------- 32x32 tiled transpose: adj [N1,N2] -> adjT [N2,N1] -------
__global__ __launch_bounds__(256) void transpose_adj(const float* __restrict__ in)
{
    __shared__ float tile[32][33];
    int x = blockIdx.x * 32 + threadIdx.x;   // col in adj
    int y = blockIdx.y * 32 + threadIdx.y;   // row in adj
    #pragma unroll
    for (int r = 0; r < 32; r += 8)
        tile[threadIdx.y + r][threadIdx.x] = in[(size_t)(y + r) * N2 + x];
    __syncthreads();
    int xo = blockIdx.y * 32 + threadIdx.x;  // col in adjT
    int yo = blockIdx.x * 32 + threadIdx.y;  // row in adjT
    #pragma unroll
    for (int r = 0; r < 32; r += 8)
        g_adjT[(size_t)(yo + r) * N1 + xo] = tile[threadIdx.x][threadIdx.y + r];
}

// --------- ordered (deterministic) per-row nonzero compaction --------------
// One block per row; emits indices in ascending column order via ballot-scan.
__global__ __launch_bounds__(256) void scan_rows(
    const float* __restrict__ A, int width,
    int* __restrict__ cnts, int* __restrict__ idxs, int cap)
{
    int r = blockIdx.x;
    const float* row = A + (size_t)r * width;
    int* myidx = idxs + (size_t)r * cap;

    __shared__ int warpCnt[8];
    __shared__ int s_total;
    if (threadIdx.x == 0) s_total = 0;
    __syncthreads();

    int lane = threadIdx.x & 31;
    int w    = threadIdx.x >> 5;
    unsigned lmask = (1u << lane) - 1u;

    for (int base = 0; base < width; base += 256) {
        int j = base + threadIdx.x;
        bool p = row[j] > 0.0f;
        unsigned m = __ballot_sync(0xffffffffu, p);
        if (lane == 0) warpCnt[w] = __popc(m);
        __syncthreads();

        int off = 0, tot = 0;
        #pragma unroll
        for (int ww = 0; ww < 8; ww++) {
            int c = warpCnt[ww];
            if (ww < w) off += c;
            tot += c;
        }
        int gbase = s_total;
        if (p) {
            int pos = gbase + off + __popc(m & lmask);
            if (pos < cap) myidx[pos] = j;
        }
        __syncthreads();
        if (threadIdx.x == 0) s_total = gbase + tot;
        __syncthreads();
    }
    if (threadIdx.x == 0) cnts[r] = s_total;
}

// ------------- edge[i,:] = (sum over row nbrs of x_4att) / degree ----------
__global__ __launch_bounds__(256) void edge_gather()
{
    int i   = blockIdx.x;
    int tid = threadIdx.x;
    __shared__ int sidx[MAXR];

    int ctrue = g_rowcnt[i];
    int c = ctrue > MAXR ? MAXR : ctrue;
    for (int k = tid; k < c; k += 256)
        sidx[k] = g_rowidx[(size_t)i * MAXR + k];
    __syncthreads();

    float acc = 0.0f;
    #pragma unroll 4
    for (int k = 0; k < c; k++)
        acc += g_x4att[(size_t)sidx[k] * 256 + tid];

    g_edge[(size_t)i * 256 + tid] = acc / (float)ctrue;
}

// ------------- per-row dot with a 256-vector (one warp per row) ------------
__global__ __launch_bounds__(256) void rowdot(
    const float* __restrict__ Mx, const float* __restrict__ v,
    float* __restrict__ o, int rows)
{
    int gw   = (blockIdx.x * blockDim.x + threadIdx.x) >> 5;
    int lane = threadIdx.x & 31;
    if (gw >= rows) return;
    const float* rw = Mx + (size_t)gw * 256;
    float s = 0.0f;
    #pragma unroll
    for (int k = 0; k < 8; k++) s += rw[lane + 32 * k] * v[lane + 32 * k];
    #pragma unroll
    for (int off = 16; off; off >>= 1) s += __shfl_down_sync(0xffffffffu, s, off);
    if (lane == 0) o[gw] = s;
}

// ------ per-column sparse softmax + weighted gather + leaky_relu out -------
__global__ __launch_bounds__(256) void attn_out(float* __restrict__ out)
{
    int j   = blockIdx.x;
    int tid = threadIdx.x;

    int c = g_colcnt[j];
    if (c > MAXC) c = MAXC;
    float snj = g_sn[j];

    __shared__ float redm[256];
    __shared__ float reds[256];
    __shared__ int   sidx[256];
    __shared__ float sw[256];

    float acc = 0.0f;

    if (c == 0) {
        // all masked: softmax over constant -9e15 -> uniform over N1
        for (int i = 0; i < N1; i++) acc += g_edge4[(size_t)i * 256 + tid];
        acc *= (1.0f / (float)N1);
    } else {
        // pass 1: online (max, sum) per thread, then block reduce
        float m = -INFINITY, s = 0.0f;
        for (int k = tid; k < c; k += 256) {
            int idx = g_colidx[(size_t)j * MAXC + k];
            float p = g_se[idx] + snj;
            p = p > 0.0f ? p : ALPHA * p;
            if (p > m) { s = s * expf(m - p) + 1.0f; m = p; }
            else       { s += expf(p - m); }
        }
        redm[tid] = m; reds[tid] = s;
        __syncthreads();
        for (int off = 128; off; off >>= 1) {
            if (tid < off) {
                float m1 = redm[tid], s1 = reds[tid];
                float m2 = redm[tid + off], s2 = reds[tid + off];
                float mm = fmaxf(m1, m2);
                float ss = 0.0f;
                if (s1 > 0.0f) ss += s1 * expf(m1 - mm);
                if (s2 > 0.0f) ss += s2 * expf(m2 - mm);
                redm[tid] = mm; reds[tid] = ss;
            }
            __syncthreads();
        }
        float M = redm[0];
        float invS = 1.0f / reds[0];

        // pass 2: chunked weighted gather of edge_4att rows
        for (int base = 0; base < c; base += 256) {
            int k = base + tid;
            if (k < c) {
                int idx = g_colidx[(size_t)j * MAXC + k];
                float p = g_se[idx] + snj;
                p = p > 0.0f ? p : ALPHA * p;
                sw[tid]   = expf(p - M) * invS;
                sidx[tid] = idx;
            }
            __syncthreads();
            int cnt = c - base; if (cnt > 256) cnt = 256;
            #pragma unroll 4
            for (int t = 0; t < cnt; t++)
                acc += sw[t] * g_edge4[(size_t)sidx[t] * 256 + tid];
            __syncthreads();
        }
    }

    out[(size_t)j * 256 + tid] = acc > 0.0f ? acc : ALPHA * acc;
}

// ---------------------------------------------------------------------------
extern "C" void kernel_launch(void* const* d_in, const int* in_sizes, int n_in,
                              void* d_out, int out_size)
{
    const float* x    = (const float*)d_in[0];   // [N2, 256]
    const float* adj  = (const float*)d_in[1];   // [N1, N2]
    const float* Wv2e = (const float*)d_in[2];   // [256, 256]
    const float* We2v = (const float*)d_in[3];   // [256, 256]
    const float* a    = (const float*)d_in[4];   // [1, 512]
    float* out = (float*)d_out;                  // [N2, 256]

    void *px4, *pedge, *pedge4, *padjT, *psn, *pse, *prc, *pcc, *pri, *pci;
    cudaGetSymbolAddress(&px4,   g_x4att);
    cudaGetSymbolAddress(&pedge, g_edge);
    cudaGetSymbolAddress(&pedge4,g_edge4);
    cudaGetSymbolAddress(&padjT, g_adjT);
    cudaGetSymbolAddress(&psn,   g_sn);
    cudaGetSymbolAddress(&pse,   g_se);
    cudaGetSymbolAddress(&prc,   g_rowcnt);
    cudaGetSymbolAddress(&pcc,   g_colcnt);
    cudaGetSymbolAddress(&pri,   g_rowidx);
    cudaGetSymbolAddress(&pci,   g_colidx);

    // 1) x_4att = x @ W_v2e
    sgemm256<<<dim3(256 / 64, N2 / 64), 256>>>(x, Wv2e, (float*)px4);

    // 2) sparsity extraction: row lists, transpose, column lists
    scan_rows<<<N1, 256>>>(adj, N2, (int*)prc, (int*)pri, MAXR);
    transpose_adj<<<dim3(N2 / 32, N1 / 32), dim3(32, 8)>>>(adj);
    scan_rows<<<N2, 256>>>((const float*)padjT, N1, (int*)pcc, (int*)pci, MAXC);

    // 3) edge = (adj @ x_4att) / degree   (sparse gather)
    edge_gather<<<N1, 256>>>();

    // 4) edge_4att = edge @ W_e2v
    sgemm256<<<dim3(256 / 64, N1 / 64), 256>>>((const float*)pedge, We2v, (float*)pedge4);

    // 5) attention logits components
    rowdot<<<N2 / 8, 256>>>((const float*)px4,    a,       (float*)psn, N2);
    rowdot<<<N1 / 8, 256>>>((const float*)pedge4, a + 256, (float*)pse, N1);

    // 6) per-column softmax + weighted gather + final leaky_relu
    attn_out<<<N2, 256>>>(out);
}

// round 7
// speedup vs baseline: 1.2552x; 1.2552x over previous
#include <cuda_runtime.h>
#include <cuda_bf16.h>
#include <math.h>

// Problem shapes (fixed by the reference)
#define N1 4096
#define N2 8192
#define D  256
#define ALPHA 0.2f

#define MAXR   256   // max nonzeros per adj row (mean ~83, max ~130)
#define CHUNKS 16    // row chunks for the column scan (N1/CHUNKS = 256)
#define CHROWS 256

// ---------------- scratch (device globals: allocation-free) ----------------
__device__ float g_x4att[(size_t)N2 * D];           // 8 MB
__device__ float g_edge [(size_t)N1 * D];           // 4 MB
__device__ float g_edge4[(size_t)N1 * D];           // 4 MB
__device__ float g_sn[N2];
__device__ float g_se[N1];
__device__ int   g_rowcnt[N1];
__device__ int   g_colcnt[N2 * CHUNKS];             // per (col, chunk) counts
__device__ int   g_rowidx[(size_t)N1 * MAXR];       // 4 MB
__device__ int   g_colidx[(size_t)N2 * N1];         // 128 MB: [col][chunk*256 + t]

// ---------------- SGEMM: C[M,256] = A[M,256] @ B[256,256] ------------------
// 64x64 tile, BK=16, 256 threads, 4x4 register microtile.
__global__ __launch_bounds__(256) void sgemm256(
    const float* __restrict__ A, const float* __restrict__ B,
    float* __restrict__ C)
{
    __shared__ __align__(16) float As[16][68];
    __shared__ __align__(16) float Bs[16][64];

    int tid  = threadIdx.x;
    int tx   = tid & 15;
    int ty   = tid >> 4;
    int row0 = blockIdx.y * 64;
    int col0 = blockIdx.x * 64;

    int arow = tid >> 2;
    int akq  = (tid & 3) << 2;
    int brow = tid >> 4;
    int bcol = (tid & 15) << 2;

    float acc[4][4];
    #pragma unroll
    for (int r = 0; r < 4; r++)
        #pragma unroll
        for (int c = 0; c < 4; c++) acc[r][c] = 0.0f;

    for (int kb = 0; kb < 256; kb += 16) {
        float4 av = *(const float4*)(A + (size_t)(row0 + arow) * 256 + kb + akq);
        As[akq + 0][arow] = av.x;
        As[akq + 1][arow] = av.y;
        As[akq + 2][arow] = av.z;
        As[akq + 3][arow] = av.w;
        *(float4*)(&Bs[brow][bcol]) =
            *(const float4*)(B + (size_t)(kb + brow) * 256 + col0 + bcol);
        __syncthreads();

        #pragma unroll
        for (int kk = 0; kk < 16; kk++) {
            float4 a = *(const float4*)(&As[kk][ty << 2]);
            float4 b = *(const float4*)(&Bs[kk][tx << 2]);
            acc[0][0] += a.x * b.x; acc[0][1] += a.x * b.y; acc[0][2] += a.x * b.z; acc[0][3] += a.x * b.w;
            acc[1][0] += a.y * b.x; acc[1][1] += a.y * b.y; acc[1][2] += a.y * b.z; acc[1][3] += a.y * b.w;
            acc[2][0] += a.z * b.x; acc[2][1] += a.z * b.y; acc[2][2] += a.z * b.z; acc[2][3] += a.z * b.w;
            acc[3][0] += a.w * b.x; acc[3][1] += a.w * b.y; acc[3][2] += a.w * b.z; acc[3][3] += a.w * b.w;
        }
        __syncthreads();
    }

    #pragma unroll
    for (int r = 0; r < 4; r++) {
        float4 vv = make_float4(acc[r][0], acc[r][1], acc[r][2], acc[r][3]);
        *(float4*)(C + (size_t)(row0 + (ty << 2) + r) * 256 + col0 + (tx << 2)) = vv;
    }
}

// --------- ordered per-row nonzero compaction (float4 vectorized) ----------
// One block per row; 1024 elements per iteration; emits ascending col order.
__global__ __launch_bounds__(256) void scan_rows4(
    const float* __restrict__ A, int width,
    int* __restrict__ cnts, int* __restrict__ idxs, int cap)
{
    int r = blockIdx.x;
    const float* row = A + (size_t)r * width;
    int* myidx = idxs + (size_t)r * cap;

    __shared__ int warpCnt[8];
    __shared__ int s_total;
    if (threadIdx.x == 0) s_total = 0;
    __syncthreads();

    int lane = threadIdx.x & 31;
    int w    = threadIdx.x >> 5;
    unsigned lmask = (1u << lane) - 1u;

    for (int base = 0; base < width; base += 1024) {
        int j = base + (threadIdx.x << 2);
        float4 v = *(const float4*)(row + j);
        bool b0 = v.x > 0.0f, b1 = v.y > 0.0f, b2 = v.z > 0.0f, b3 = v.w > 0.0f;
        unsigned m0 = __ballot_sync(0xffffffffu, b0);
        unsigned m1 = __ballot_sync(0xffffffffu, b1);
        unsigned m2 = __ballot_sync(0xffffffffu, b2);
        unsigned m3 = __ballot_sync(0xffffffffu, b3);
        int myoff = __popc(m0 & lmask) + __popc(m1 & lmask)
                  + __popc(m2 & lmask) + __popc(m3 & lmask);
        if (lane == 0)
            warpCnt[w] = __popc(m0) + __popc(m1) + __popc(m2) + __popc(m3);
        __syncthreads();

        int off = 0, tot = 0;
        #pragma unroll
        for (int ww = 0; ww < 8; ww++) {
            int c = warpCnt[ww];
            if (ww < w) off += c;
            tot += c;
        }
        int pos = s_total + off + myoff;
        if (pos + 4 <= cap) {   // fast path (always true for this data)
            if (b0) myidx[pos++] = j;
            if (b1) myidx[pos++] = j + 1;
            if (b2) myidx[pos++] = j + 2;
            if (b3) myidx[pos++] = j + 3;
        } else {
            if (b0) { if (pos < cap) myidx[pos] = j;     pos++; }
            if (b1) { if (pos < cap) myidx[pos] = j + 1; pos++; }
            if (b2) { if (pos < cap) myidx[pos] = j + 2; pos++; }
            if (b3) { if (pos < cap) myidx[pos] = j + 3; pos++; }
        }
        __syncthreads();
        if (threadIdx.x == 0) s_total += tot;
        __syncthreads();
    }
    if (threadIdx.x == 0) cnts[r] = s_total;
}

// --------- direct column-list construction (no transpose) ------------------
// Block = 256 consecutive columns x one 256-row chunk. Threads read adj
// coalesced (one row-slice per iteration); each thread appends its column's
// row indices in ascending row order into its chunk segment.
__global__ __launch_bounds__(256) void col_scan(const float* __restrict__ adj)
{
    int col  = blockIdx.x * 256 + threadIdx.x;
    int ch   = blockIdx.y;
    int row0 = ch * CHROWS;
    int* dst = g_colidx + (size_t)col * N1 + (size_t)ch * CHROWS;

    int cnt = 0;
    for (int i0 = 0; i0 < CHROWS; i0 += 8) {
        float v[8];
        #pragma unroll
        for (int q = 0; q < 8; q++)
            v[q] = adj[(size_t)(row0 + i0 + q) * N2 + col];
        #pragma unroll
        for (int q = 0; q < 8; q++)
            if (v[q] > 0.0f) dst[cnt++] = row0 + i0 + q;
    }
    g_colcnt[col * CHUNKS + ch] = cnt;
}

// ------------- edge[i,:] = (sum over row nbrs of x_4att) / degree ----------
__global__ __launch_bounds__(256) void edge_gather()
{
    int i   = blockIdx.x;
    int tid = threadIdx.x;
    __shared__ int sidx[MAXR];

    int ctrue = g_rowcnt[i];
    int c = ctrue > MAXR ? MAXR : ctrue;
    for (int k = tid; k < c; k += 256)
        sidx[k] = g_rowidx[(size_t)i * MAXR + k];
    __syncthreads();

    float acc = 0.0f;
    #pragma unroll 4
    for (int k = 0; k < c; k++)
        acc += g_x4att[(size_t)sidx[k] * 256 + tid];

    g_edge[(size_t)i * 256 + tid] = acc / (float)ctrue;
}

// ------------- per-row dot with a 256-vector (one warp per row) ------------
__global__ __launch_bounds__(256) void rowdot(
    const float* __restrict__ Mx, const float* __restrict__ v,
    float* __restrict__ o, int rows)
{
    int gw   = (blockIdx.x * blockDim.x + threadIdx.x) >> 5;
    int lane = threadIdx.x & 31;
    if (gw >= rows) return;
    const float* rw = Mx + (size_t)gw * 256;
    float s = 0.0f;
    #pragma unroll
    for (int k = 0; k < 8; k++) s += rw[lane + 32 * k] * v[lane + 32 * k];
    #pragma unroll
    for (int off = 16; off; off >>= 1) s += __shfl_down_sync(0xffffffffu, s, off);
    if (lane == 0) o[gw] = s;
}

// ------ per-column sparse softmax + weighted gather + leaky_relu out -------
__global__ __launch_bounds__(256) void attn_out(float* __restrict__ out)
{
    int j   = blockIdx.x;
    int tid = threadIdx.x;

    __shared__ int   sidx[N1];      // 16 KB (col 0 holds all 4096 rows)
    __shared__ float sw  [N1];      // 16 KB
    __shared__ float redm[256];
    __shared__ float reds[256];
    __shared__ int   s_off[CHUNKS + 1];

    // concatenate the 16 ordered chunk segments -> fully row-ordered list
    if (tid == 0) {
        int t = 0;
        #pragma unroll
        for (int ch = 0; ch < CHUNKS; ch++) {
            s_off[ch] = t;
            t += g_colcnt[j * CHUNKS + ch];
        }
        s_off[CHUNKS] = t;
    }
    __syncthreads();
    int c = s_off[CHUNKS];

    for (int ch = 0; ch < CHUNKS; ch++) {
        int cnt = s_off[ch + 1] - s_off[ch];
        const int* src = g_colidx + (size_t)j * N1 + (size_t)ch * CHROWS;
        for (int k = tid; k < cnt; k += 256)
            sidx[s_off[ch] + k] = src[k];
    }
    __syncthreads();

    float snj = g_sn[j];
    float acc = 0.0f;

    if (c == 0) {
        // all masked: softmax over constant -> uniform over N1
        for (int i = 0; i < N1; i++) acc += g_edge4[(size_t)i * 256 + tid];
        acc *= (1.0f / (float)N1);
    } else {
        // pass 1: online (max, sum) per thread, then block reduce
        float m = -INFINITY, s = 0.0f;
        for (int k = tid; k < c; k += 256) {
            float p = g_se[sidx[k]] + snj;
            p = p > 0.0f ? p : ALPHA * p;
            if (p > m) { s = s * expf(m - p) + 1.0f; m = p; }
            else       { s += expf(p - m); }
        }
        redm[tid] = m; reds[tid] = s;
        __syncthreads();
        for (int off = 128; off; off >>= 1) {
            if (tid < off) {
                float m1 = redm[tid], s1 = reds[tid];
                float m2 = redm[tid + off], s2 = reds[tid + off];
                float mm = fmaxf(m1, m2);
                float ss = 0.0f;
                if (s1 > 0.0f) ss += s1 * expf(m1 - mm);
                if (s2 > 0.0f) ss += s2 * expf(m2 - mm);
                redm[tid] = mm; reds[tid] = ss;
            }
            __syncthreads();
        }
        float M = redm[0];
        float invS = 1.0f / reds[0];

        // weights (once)
        for (int k = tid; k < c; k += 256) {
            float p = g_se[sidx[k]] + snj;
            p = p > 0.0f ? p : ALPHA * p;
            sw[k] = expf(p - M) * invS;
        }
        __syncthreads();

        // broadcast gather of edge_4att rows
        #pragma unroll 4
        for (int t = 0; t < c; t++)
            acc += sw[t] * g_edge4[(size_t)sidx[t] * 256 + tid];
    }

    out[(size_t)j * 256 + tid] = acc > 0.0f ? acc : ALPHA * acc;
}

// ---------------------------------------------------------------------------
extern "C" void kernel_launch(void* const* d_in, const int* in_sizes, int n_in,
                              void* d_out, int out_size)
{
    const float* x    = (const float*)d_in[0];   // [N2, 256]
    const float* adj  = (const float*)d_in[1];   // [N1, N2]
    const float* Wv2e = (const float*)d_in[2];   // [256, 256]
    const float* We2v = (const float*)d_in[3];   // [256, 256]
    const float* a    = (const float*)d_in[4];   // [1, 512]
    float* out = (float*)d_out;                  // [N2, 256]

    void *px4, *pedge, *pedge4, *psn, *pse, *prc, *pri;
    cudaGetSymbolAddress(&px4,   g_x4att);
    cudaGetSymbolAddress(&pedge, g_edge);
    cudaGetSymbolAddress(&pedge4,g_edge4);
    cudaGetSymbolAddress(&psn,   g_sn);
    cudaGetSymbolAddress(&pse,   g_se);
    cudaGetSymbolAddress(&prc,   g_rowcnt);
    cudaGetSymbolAddress(&pri,   g_rowidx);

    // 1) x_4att = x @ W_v2e
    sgemm256<<<dim3(256 / 64, N2 / 64), 256>>>(x, Wv2e, (float*)px4);

    // 2) sparsity extraction: row lists + direct column lists (no transpose)
    scan_rows4<<<N1, 256>>>(adj, N2, (int*)prc, (int*)pri, MAXR);
    col_scan<<<dim3(N2 / 256, CHUNKS), 256>>>(adj);

    // 3) edge = (adj @ x_4att) / degree   (sparse gather)
    edge_gather<<<N1, 256>>>();

    // 4) edge_4att = edge @ W_e2v
    sgemm256<<<dim3(256 / 64, N1 / 64), 256>>>((const float*)pedge, We2v, (float*)pedge4);

    // 5) attention logits components
    rowdot<<<N2 / 8, 256>>>((const float*)px4,    a,       (float*)psn, N2);
    rowdot<<<N1 / 8, 256>>>((const float*)pedge4, a + 256, (float*)pse, N1);

    // 6) per-column softmax + weighted gather + final leaky_relu
    attn_out<<<N2, 256>>>(out);
}

// round 8
// speedup vs baseline: 1.8564x; 1.4790x over previous
#include <cuda_runtime.h>
#include <cuda_bf16.h>
#include <math.h>

// Problem shapes (fixed by the reference)
#define N1 4096
#define N2 8192
#define D  256
#define ALPHA 0.2f

#define MAXR   256   // max nonzeros per adj row (mean ~83, max ~130)
#define CHUNKS 16    // row chunks for the column scan (N1/CHUNKS = 256)
#define CHROWS 256

// ---------------- scratch (device globals: allocation-free) ----------------
__device__ float g_x4att[(size_t)N2 * D];           // 8 MB
__device__ float g_edge [(size_t)N1 * D];           // 4 MB
__device__ float g_edge4[(size_t)N1 * D];           // 4 MB
__device__ float g_sn[N2];
__device__ float g_se[N1];
__device__ int   g_rowcnt[N1];
__device__ int   g_colcnt[N2 * CHUNKS];             // per (col, chunk) counts
__device__ int   g_rowidx[(size_t)N1 * MAXR];       // 4 MB
__device__ int   g_colidx[(size_t)N2 * N1];         // 128 MB: [col][chunk*256 + t]

// ---------------- SGEMM: C[M,256] = A[M,256] @ B[256,256] ------------------
__global__ __launch_bounds__(256) void sgemm256(
    const float* __restrict__ A, const float* __restrict__ B,
    float* __restrict__ C)
{
    __shared__ __align__(16) float As[16][68];
    __shared__ __align__(16) float Bs[16][64];

    int tid  = threadIdx.x;
    int tx   = tid & 15;
    int ty   = tid >> 4;
    int row0 = blockIdx.y * 64;
    int col0 = blockIdx.x * 64;

    int arow = tid >> 2;
    int akq  = (tid & 3) << 2;
    int brow = tid >> 4;
    int bcol = (tid & 15) << 2;

    float acc[4][4];
    #pragma unroll
    for (int r = 0; r < 4; r++)
        #pragma unroll
        for (int c = 0; c < 4; c++) acc[r][c] = 0.0f;

    for (int kb = 0; kb < 256; kb += 16) {
        float4 av = *(const float4*)(A + (size_t)(row0 + arow) * 256 + kb + akq);
        As[akq + 0][arow] = av.x;
        As[akq + 1][arow] = av.y;
        As[akq + 2][arow] = av.z;
        As[akq + 3][arow] = av.w;
        *(float4*)(&Bs[brow][bcol]) =
            *(const float4*)(B + (size_t)(kb + brow) * 256 + col0 + bcol);
        __syncthreads();

        #pragma unroll
        for (int kk = 0; kk < 16; kk++) {
            float4 a = *(const float4*)(&As[kk][ty << 2]);
            float4 b = *(const float4*)(&Bs[kk][tx << 2]);
            acc[0][0] += a.x * b.x; acc[0][1] += a.x * b.y; acc[0][2] += a.x * b.z; acc[0][3] += a.x * b.w;
            acc[1][0] += a.y * b.x; acc[1][1] += a.y * b.y; acc[1][2] += a.y * b.z; acc[1][3] += a.y * b.w;
            acc[2][0] += a.z * b.x; acc[2][1] += a.z * b.y; acc[2][2] += a.z * b.z; acc[2][3] += a.z * b.w;
            acc[3][0] += a.w * b.x; acc[3][1] += a.w * b.y; acc[3][2] += a.w * b.z; acc[3][3] += a.w * b.w;
        }
        __syncthreads();
    }

    #pragma unroll
    for (int r = 0; r < 4; r++) {
        float4 vv = make_float4(acc[r][0], acc[r][1], acc[r][2], acc[r][3]);
        *(float4*)(C + (size_t)(row0 + (ty << 2) + r) * 256 + col0 + (tx << 2)) = vv;
    }
}

// --------- ordered per-row nonzero compaction (float4 vectorized) ----------
__global__ __launch_bounds__(256) void scan_rows4(
    const float* __restrict__ A, int width,
    int* __restrict__ cnts, int* __restrict__ idxs, int cap)
{
    int r = blockIdx.x;
    const float* row = A + (size_t)r * width;
    int* myidx = idxs + (size_t)r * cap;

    __shared__ int warpCnt[8];
    __shared__ int s_total;
    if (threadIdx.x == 0) s_total = 0;
    __syncthreads();

    int lane = threadIdx.x & 31;
    int w    = threadIdx.x >> 5;
    unsigned lmask = (1u << lane) - 1u;

    for (int base = 0; base < width; base += 1024) {
        int j = base + (threadIdx.x << 2);
        float4 v = *(const float4*)(row + j);
        bool b0 = v.x > 0.0f, b1 = v.y > 0.0f, b2 = v.z > 0.0f, b3 = v.w > 0.0f;
        unsigned m0 = __ballot_sync(0xffffffffu, b0);
        unsigned m1 = __ballot_sync(0xffffffffu, b1);
        unsigned m2 = __ballot_sync(0xffffffffu, b2);
        unsigned m3 = __ballot_sync(0xffffffffu, b3);
        int myoff = __popc(m0 & lmask) + __popc(m1 & lmask)
                  + __popc(m2 & lmask) + __popc(m3 & lmask);
        if (lane == 0)
            warpCnt[w] = __popc(m0) + __popc(m1) + __popc(m2) + __popc(m3);
        __syncthreads();

        int off = 0, tot = 0;
        #pragma unroll
        for (int ww = 0; ww < 8; ww++) {
            int c = warpCnt[ww];
            if (ww < w) off += c;
            tot += c;
        }
        int pos = s_total + off + myoff;
        if (pos + 4 <= cap) {
            if (b0) myidx[pos++] = j;
            if (b1) myidx[pos++] = j + 1;
            if (b2) myidx[pos++] = j + 2;
            if (b3) myidx[pos++] = j + 3;
        } else {
            if (b0) { if (pos < cap) myidx[pos] = j;     pos++; }
            if (b1) { if (pos < cap) myidx[pos] = j + 1; pos++; }
            if (b2) { if (pos < cap) myidx[pos] = j + 2; pos++; }
            if (b3) { if (pos < cap) myidx[pos] = j + 3; pos++; }
        }
        __syncthreads();
        if (threadIdx.x == 0) s_total += tot;
        __syncthreads();
    }
    if (threadIdx.x == 0) cnts[r] = s_total;
}

// --------- direct column-list construction (no transpose) ------------------
__global__ __launch_bounds__(256) void col_scan(const float* __restrict__ adj)
{
    int col  = blockIdx.x * 256 + threadIdx.x;
    int ch   = blockIdx.y;
    int row0 = ch * CHROWS;
    int* dst = g_colidx + (size_t)col * N1 + (size_t)ch * CHROWS;

    int cnt = 0;
    for (int i0 = 0; i0 < CHROWS; i0 += 8) {
        float v[8];
        #pragma unroll
        for (int q = 0; q < 8; q++)
            v[q] = adj[(size_t)(row0 + i0 + q) * N2 + col];
        #pragma unroll
        for (int q = 0; q < 8; q++)
            if (v[q] > 0.0f) dst[cnt++] = row0 + i0 + q;
    }
    g_colcnt[col * CHUNKS + ch] = cnt;
}

// ------------- edge[i,:] = (sum over row nbrs of x_4att) / degree ----------
// 4-way neighbor split x float4 columns: thread (s=tid>>6, g=tid&63)
// accumulates rows k = s, s+4, ... at float4 column group g.
__global__ __launch_bounds__(256) void edge_gather()
{
    int i   = blockIdx.x;
    int tid = threadIdx.x;
    int g   = tid & 63;
    int s   = tid >> 6;

    __shared__ int sidx[MAXR];
    __shared__ __align__(16) float4 part[256];

    int ctrue = g_rowcnt[i];
    int c = ctrue > MAXR ? MAXR : ctrue;
    for (int k = tid; k < c; k += 256)
        sidx[k] = g_rowidx[(size_t)i * MAXR + k];
    __syncthreads();

    float4 acc = make_float4(0.f, 0.f, 0.f, 0.f);
    int k = s;
    for (; k + 12 < c; k += 16) {
        const float4 v0 = *(const float4*)(g_x4att + (size_t)sidx[k     ] * 256 + (g << 2));
        const float4 v1 = *(const float4*)(g_x4att + (size_t)sidx[k + 4 ] * 256 + (g << 2));
        const float4 v2 = *(const float4*)(g_x4att + (size_t)sidx[k + 8 ] * 256 + (g << 2));
        const float4 v3 = *(const float4*)(g_x4att + (size_t)sidx[k + 12] * 256 + (g << 2));
        acc.x += v0.x + v1.x + v2.x + v3.x;
        acc.y += v0.y + v1.y + v2.y + v3.y;
        acc.z += v0.z + v1.z + v2.z + v3.z;
        acc.w += v0.w + v1.w + v2.w + v3.w;
    }
    for (; k < c; k += 4) {
        const float4 v = *(const float4*)(g_x4att + (size_t)sidx[k] * 256 + (g << 2));
        acc.x += v.x; acc.y += v.y; acc.z += v.z; acc.w += v.w;
    }
    part[tid] = acc;
    __syncthreads();

    if (s == 0) {
        float4 a0 = part[g], a1 = part[64 + g], a2 = part[128 + g], a3 = part[192 + g];
        float inv = 1.0f / (float)ctrue;
        float4 o;
        o.x = (a0.x + a1.x + a2.x + a3.x) * inv;
        o.y = (a0.y + a1.y + a2.y + a3.y) * inv;
        o.z = (a0.z + a1.z + a2.z + a3.z) * inv;
        o.w = (a0.w + a1.w + a2.w + a3.w) * inv;
        *(float4*)(g_edge + (size_t)i * 256 + (g << 2)) = o;
    }
}

// ------------- per-row dot with a 256-vector (one warp per row) ------------
__global__ __launch_bounds__(256) void rowdot(
    const float* __restrict__ Mx, const float* __restrict__ v,
    float* __restrict__ o, int rows)
{
    int gw   = (blockIdx.x * blockDim.x + threadIdx.x) >> 5;
    int lane = threadIdx.x & 31;
    if (gw >= rows) return;
    const float* rw = Mx + (size_t)gw * 256;
    float s = 0.0f;
    #pragma unroll
    for (int k = 0; k < 8; k++) s += rw[lane + 32 * k] * v[lane + 32 * k];
    #pragma unroll
    for (int off = 16; off; off >>= 1) s += __shfl_down_sync(0xffffffffu, s, off);
    if (lane == 0) o[gw] = s;
}

// ------ per-column sparse softmax + weighted gather + leaky_relu out -------
__global__ __launch_bounds__(256) void attn_out(float* __restrict__ out)
{
    int j   = blockIdx.x;
    int tid = threadIdx.x;
    int g   = tid & 63;
    int s   = tid >> 6;

    __shared__ int   sidx[N1];      // 16 KB
    __shared__ float sw  [N1];      // 16 KB
    __shared__ float redm[256];
    __shared__ float reds[256];
    __shared__ __align__(16) float4 part[256];   // 4 KB
    __shared__ int   s_off[CHUNKS + 1];

    if (tid == 0) {
        int t = 0;
        #pragma unroll
        for (int ch = 0; ch < CHUNKS; ch++) {
            s_off[ch] = t;
            t += g_colcnt[j * CHUNKS + ch];
        }
        s_off[CHUNKS] = t;
    }
    __syncthreads();
    int c = s_off[CHUNKS];

    for (int ch = 0; ch < CHUNKS; ch++) {
        int cnt = s_off[ch + 1] - s_off[ch];
        const int* src = g_colidx + (size_t)j * N1 + (size_t)ch * CHROWS;
        for (int k = tid; k < cnt; k += 256)
            sidx[s_off[ch] + k] = src[k];
    }
    __syncthreads();

    float snj = g_sn[j];
    float4 acc = make_float4(0.f, 0.f, 0.f, 0.f);

    if (c == 0) {
        // all masked: softmax over constant -> uniform over N1
        for (int i = s; i < N1; i += 4) {
            const float4 v = *(const float4*)(g_edge4 + (size_t)i * 256 + (g << 2));
            acc.x += v.x; acc.y += v.y; acc.z += v.z; acc.w += v.w;
        }
        acc.x *= (1.0f / N1); acc.y *= (1.0f / N1);
        acc.z *= (1.0f / N1); acc.w *= (1.0f / N1);
    } else {
        // pass 1: online (max, sum) per thread, then block reduce
        float m = -INFINITY, sm = 0.0f;
        for (int k = tid; k < c; k += 256) {
            float p = g_se[sidx[k]] + snj;
            p = p > 0.0f ? p : ALPHA * p;
            if (p > m) { sm = sm * expf(m - p) + 1.0f; m = p; }
            else       { sm += expf(p - m); }
        }
        redm[tid] = m; reds[tid] = sm;
        __syncthreads();
        for (int off = 128; off; off >>= 1) {
            if (tid < off) {
                float m1 = redm[tid], s1 = reds[tid];
                float m2 = redm[tid + off], s2 = reds[tid + off];
                float mm = fmaxf(m1, m2);
                float ss = 0.0f;
                if (s1 > 0.0f) ss += s1 * expf(m1 - mm);
                if (s2 > 0.0f) ss += s2 * expf(m2 - mm);
                redm[tid] = mm; reds[tid] = ss;
            }
            __syncthreads();
        }
        float M = redm[0];
        float invS = 1.0f / reds[0];

        // weights (once)
        for (int k = tid; k < c; k += 256) {
            float p = g_se[sidx[k]] + snj;
            p = p > 0.0f ? p : ALPHA * p;
            sw[k] = expf(p - M) * invS;
        }
        __syncthreads();

        // weighted gather: 4-way neighbor split x float4 columns
        int k = s;
        for (; k + 12 < c; k += 16) {
            int   i0 = sidx[k],      i1 = sidx[k + 4], i2 = sidx[k + 8], i3 = sidx[k + 12];
            float w0 = sw[k],        w1 = sw[k + 4],   w2 = sw[k + 8],   w3 = sw[k + 12];
            const float4 v0 = *(const float4*)(g_edge4 + (size_t)i0 * 256 + (g << 2));
            const float4 v1 = *(const float4*)(g_edge4 + (size_t)i1 * 256 + (g << 2));
            const float4 v2 = *(const float4*)(g_edge4 + (size_t)i2 * 256 + (g << 2));
            const float4 v3 = *(const float4*)(g_edge4 + (size_t)i3 * 256 + (g << 2));
            acc.x += w0 * v0.x + w1 * v1.x + w2 * v2.x + w3 * v3.x;
            acc.y += w0 * v0.y + w1 * v1.y + w2 * v2.y + w3 * v3.y;
            acc.z += w0 * v0.z + w1 * v1.z + w2 * v2.z + w3 * v3.z;
            acc.w += w0 * v0.w + w1 * v1.w + w2 * v2.w + w3 * v3.w;
        }
        for (; k < c; k += 4) {
            float wk = sw[k];
            const float4 v = *(const float4*)(g_edge4 + (size_t)sidx[k] * 256 + (g << 2));
            acc.x += wk * v.x; acc.y += wk * v.y; acc.z += wk * v.z; acc.w += wk * v.w;
        }
    }

    part[tid] = acc;
    __syncthreads();

    if (s == 0) {
        float4 a0 = part[g], a1 = part[64 + g], a2 = part[128 + g], a3 = part[192 + g];
        float4 o;
        o.x = a0.x + a1.x + a2.x + a3.x;
        o.y = a0.y + a1.y + a2.y + a3.y;
        o.z = a0.z + a1.z + a2.z + a3.z;
        o.w = a0.w + a1.w + a2.w + a3.w;
        o.x = o.x > 0.0f ? o.x : ALPHA * o.x;
        o.y = o.y > 0.0f ? o.y : ALPHA * o.y;
        o.z = o.z > 0.0f ? o.z : ALPHA * o.z;
        o.w = o.w > 0.0f ? o.w : ALPHA * o.w;
        *(float4*)(out + (size_t)j * 256 + (g << 2)) = o;
    }
}

// ---------------------------------------------------------------------------
extern "C" void kernel_launch(void* const* d_in, const int* in_sizes, int n_in,
                              void* d_out, int out_size)
{
    const float* x    = (const float*)d_in[0];   // [N2, 256]
    const float* adj  = (const float*)d_in[1];   // [N1, N2]
    const float* Wv2e = (const float*)d_in[2];   // [256, 256]
    const float* We2v = (const float*)d_in[3];   // [256, 256]
    const float* a    = (const float*)d_in[4];   // [1, 512]
    float* out = (float*)d_out;                  // [N2, 256]

    void *px4, *pedge, *pedge4, *psn, *pse, *prc, *pri;
    cudaGetSymbolAddress(&px4,   g_x4att);
    cudaGetSymbolAddress(&pedge, g_edge);
    cudaGetSymbolAddress(&pedge4,g_edge4);
    cudaGetSymbolAddress(&psn,   g_sn);
    cudaGetSymbolAddress(&pse,   g_se);
    cudaGetSymbolAddress(&prc,   g_rowcnt);
    cudaGetSymbolAddress(&pri,   g_rowidx);

    // 1) x_4att = x @ W_v2e
    sgemm256<<<dim3(256 / 64, N2 / 64), 256>>>(x, Wv2e, (float*)px4);

    // 2) sparsity extraction: row lists + direct column lists (no transpose)
    scan_rows4<<<N1, 256>>>(adj, N2, (int*)prc, (int*)pri, MAXR);
    col_scan<<<dim3(N2 / 256, CHUNKS), 256>>>(adj);

    // 3) edge = (adj @ x_4att) / degree   (sparse gather)
    edge_gather<<<N1, 256>>>();

    // 4) edge_4att = edge @ W_e2v
    sgemm256<<<dim3(256 / 64, N1 / 64), 256>>>((const float*)pedge, We2v, (float*)pedge4);

    // 5) attention logits components
    rowdot<<<N2 / 8, 256>>>((const float*)px4,    a,       (float*)psn, N2);
    rowdot<<<N1 / 8, 256>>>((const float*)pedge4, a + 256, (float*)pse, N1);

    // 6) per-column softmax + weighted gather + final leaky_relu
    attn_out<<<N2, 256>>>(out);
}

// round 9
// speedup vs baseline: 2.2692x; 1.2223x over previous
#include <cuda_runtime.h>
#include <cuda_bf16.h>
#include <math.h>

// Problem shapes (fixed by the reference)
#define N1 4096
#define N2 8192
#define D  256
#define ALPHA 0.2f

#define MAXR   256   // max nonzeros per adj row (mean ~83, max ~130)
#define CHUNKS 16    // row chunks for the column scan (N1/CHUNKS = 256)
#define CHROWS 256

// ---------------- scratch (device globals: allocation-free) ----------------
__device__ float g_x4att[(size_t)N2 * D];           // 8 MB
__device__ float g_edge [(size_t)N1 * D];           // 4 MB
__device__ float g_edge4[(size_t)N1 * D];           // 4 MB
__device__ float g_sn[N2];
__device__ float g_se[N1];
__device__ int   g_rowcnt[N1];
__device__ int   g_colcnt[N2 * CHUNKS];             // per (col, chunk) counts
__device__ int   g_rowidx[(size_t)N1 * MAXR];       // 4 MB
__device__ int   g_colidx[(size_t)N2 * N1];         // 128 MB: [col][chunk*256 + t]

// ---------------- SGEMM: C[M,256] = A[M,256] @ B[256,256] ------------------
__global__ __launch_bounds__(256) void sgemm256(
    const float* __restrict__ A, const float* __restrict__ B,
    float* __restrict__ C)
{
    __shared__ __align__(16) float As[16][68];
    __shared__ __align__(16) float Bs[16][64];

    int tid  = threadIdx.x;
    int tx   = tid & 15;
    int ty   = tid >> 4;
    int row0 = blockIdx.y * 64;
    int col0 = blockIdx.x * 64;

    int arow = tid >> 2;
    int akq  = (tid & 3) << 2;
    int brow = tid >> 4;
    int bcol = (tid & 15) << 2;

    float acc[4][4];
    #pragma unroll
    for (int r = 0; r < 4; r++)
        #pragma unroll
        for (int c = 0; c < 4; c++) acc[r][c] = 0.0f;

    for (int kb = 0; kb < 256; kb += 16) {
        float4 av = *(const float4*)(A + (size_t)(row0 + arow) * 256 + kb + akq);
        As[akq + 0][arow] = av.x;
        As[akq + 1][arow] = av.y;
        As[akq + 2][arow] = av.z;
        As[akq + 3][arow] = av.w;
        *(float4*)(&Bs[brow][bcol]) =
            *(const float4*)(B + (size_t)(kb + brow) * 256 + col0 + bcol);
        __syncthreads();

        #pragma unroll
        for (int kk = 0; kk < 16; kk++) {
            float4 a = *(const float4*)(&As[kk][ty << 2]);
            float4 b = *(const float4*)(&Bs[kk][tx << 2]);
            acc[0][0] += a.x * b.x; acc[0][1] += a.x * b.y; acc[0][2] += a.x * b.z; acc[0][3] += a.x * b.w;
            acc[1][0] += a.y * b.x; acc[1][1] += a.y * b.y; acc[1][2] += a.y * b.z; acc[1][3] += a.y * b.w;
            acc[2][0] += a.z * b.x; acc[2][1] += a.z * b.y; acc[2][2] += a.z * b.z; acc[2][3] += a.z * b.w;
            acc[3][0] += a.w * b.x; acc[3][1] += a.w * b.y; acc[3][2] += a.w * b.z; acc[3][3] += a.w * b.w;
        }
        __syncthreads();
    }

    #pragma unroll
    for (int r = 0; r < 4; r++) {
        float4 vv = make_float4(acc[r][0], acc[r][1], acc[r][2], acc[r][3]);
        *(float4*)(C + (size_t)(row0 + (ty << 2) + r) * 256 + col0 + (tx << 2)) = vv;
    }
}

// --------- ordered per-row nonzero compaction (float4 vectorized) ----------
__global__ __launch_bounds__(256) void scan_rows4(
    const float* __restrict__ A, int width,
    int* __restrict__ cnts, int* __restrict__ idxs, int cap)
{
    int r = blockIdx.x;
    const float* row = A + (size_t)r * width;
    int* myidx = idxs + (size_t)r * cap;

    __shared__ int warpCnt[8];
    __shared__ int s_total;
    if (threadIdx.x == 0) s_total = 0;
    __syncthreads();

    int lane = threadIdx.x & 31;
    int w    = threadIdx.x >> 5;
    unsigned lmask = (1u << lane) - 1u;

    for (int base = 0; base < width; base += 1024) {
        int j = base + (threadIdx.x << 2);
        float4 v = *(const float4*)(row + j);
        bool b0 = v.x > 0.0f, b1 = v.y > 0.0f, b2 = v.z > 0.0f, b3 = v.w > 0.0f;
        unsigned m0 = __ballot_sync(0xffffffffu, b0);
        unsigned m1 = __ballot_sync(0xffffffffu, b1);
        unsigned m2 = __ballot_sync(0xffffffffu, b2);
        unsigned m3 = __ballot_sync(0xffffffffu, b3);
        int myoff = __popc(m0 & lmask) + __popc(m1 & lmask)
                  + __popc(m2 & lmask) + __popc(m3 & lmask);
        if (lane == 0)
            warpCnt[w] = __popc(m0) + __popc(m1) + __popc(m2) + __popc(m3);
        __syncthreads();

        int off = 0, tot = 0;
        #pragma unroll
        for (int ww = 0; ww < 8; ww++) {
            int c = warpCnt[ww];
            if (ww < w) off += c;
            tot += c;
        }
        int pos = s_total + off + myoff;
        if (pos + 4 <= cap) {
            if (b0) myidx[pos++] = j;
            if (b1) myidx[pos++] = j + 1;
            if (b2) myidx[pos++] = j + 2;
            if (b3) myidx[pos++] = j + 3;
        } else {
            if (b0) { if (pos < cap) myidx[pos] = j;     pos++; }
            if (b1) { if (pos < cap) myidx[pos] = j + 1; pos++; }
            if (b2) { if (pos < cap) myidx[pos] = j + 2; pos++; }
            if (b3) { if (pos < cap) myidx[pos] = j + 3; pos++; }
        }
        __syncthreads();
        if (threadIdx.x == 0) s_total += tot;
        __syncthreads();
    }
    if (threadIdx.x == 0) cnts[r] = s_total;
}

// --------- direct column-list construction (no transpose) ------------------
__global__ __launch_bounds__(256) void col_scan(const float* __restrict__ adj)
{
    int col  = blockIdx.x * 256 + threadIdx.x;
    int ch   = blockIdx.y;
    int row0 = ch * CHROWS;
    int* dst = g_colidx + (size_t)col * N1 + (size_t)ch * CHROWS;

    int cnt = 0;
    for (int i0 = 0; i0 < CHROWS; i0 += 8) {
        float v[8];
        #pragma unroll
        for (int q = 0; q < 8; q++)
            v[q] = adj[(size_t)(row0 + i0 + q) * N2 + col];
        #pragma unroll
        for (int q = 0; q < 8; q++)
            if (v[q] > 0.0f) dst[cnt++] = row0 + i0 + q;
    }
    g_colcnt[col * CHUNKS + ch] = cnt;
}

// ------------- edge[i,:] = (sum over row nbrs of x_4att) / degree ----------
// 4-way neighbor split x float4 columns, MLP-8 unrolled.
__global__ __launch_bounds__(256) void edge_gather()
{
    int i   = blockIdx.x;
    int tid = threadIdx.x;
    int g   = tid & 63;
    int s   = tid >> 6;

    __shared__ int sidx[MAXR];
    __shared__ __align__(16) float4 part[256];

    int ctrue = g_rowcnt[i];
    int c = ctrue > MAXR ? MAXR : ctrue;
    for (int k = tid; k < c; k += 256)
        sidx[k] = g_rowidx[(size_t)i * MAXR + k];
    __syncthreads();

    float4 acc = make_float4(0.f, 0.f, 0.f, 0.f);
    int k = s;
    for (; k + 28 < c; k += 32) {
        float4 v[8];
        #pragma unroll
        for (int q = 0; q < 8; q++)
            v[q] = *(const float4*)(g_x4att + (size_t)sidx[k + 4 * q] * 256 + (g << 2));
        #pragma unroll
        for (int q = 0; q < 8; q++) {
            acc.x += v[q].x; acc.y += v[q].y; acc.z += v[q].z; acc.w += v[q].w;
        }
    }
    for (; k < c; k += 4) {
        const float4 v = *(const float4*)(g_x4att + (size_t)sidx[k] * 256 + (g << 2));
        acc.x += v.x; acc.y += v.y; acc.z += v.z; acc.w += v.w;
    }
    part[tid] = acc;
    __syncthreads();

    if (s == 0) {
        float4 a0 = part[g], a1 = part[64 + g], a2 = part[128 + g], a3 = part[192 + g];
        float inv = 1.0f / (float)ctrue;
        float4 o;
        o.x = (a0.x + a1.x + a2.x + a3.x) * inv;
        o.y = (a0.y + a1.y + a2.y + a3.y) * inv;
        o.z = (a0.z + a1.z + a2.z + a3.z) * inv;
        o.w = (a0.w + a1.w + a2.w + a3.w) * inv;
        *(float4*)(g_edge + (size_t)i * 256 + (g << 2)) = o;
    }
}

// ------------- per-row dot with a 256-vector (one warp per row) ------------
__global__ __launch_bounds__(256) void rowdot(
    const float* __restrict__ Mx, const float* __restrict__ v,
    float* __restrict__ o, int rows)
{
    int gw   = (blockIdx.x * blockDim.x + threadIdx.x) >> 5;
    int lane = threadIdx.x & 31;
    if (gw >= rows) return;
    const float* rw = Mx + (size_t)gw * 256;
    float s = 0.0f;
    #pragma unroll
    for (int k = 0; k < 8; k++) s += rw[lane + 32 * k] * v[lane + 32 * k];
    #pragma unroll
    for (int off = 16; off; off >>= 1) s += __shfl_down_sync(0xffffffffu, s, off);
    if (lane == 0) o[gw] = s;
}

// ------ per-column sparse softmax + weighted gather + leaky_relu out -------
__global__ __launch_bounds__(256) void attn_out(float* __restrict__ out)
{
    int j    = blockIdx.x;
    int tid  = threadIdx.x;
    int g    = tid & 63;
    int s    = tid >> 6;
    int w    = tid >> 5;
    int lane = tid & 31;

    __shared__ int   sidx[N1];      // 16 KB
    __shared__ float sw  [N1];      // 16 KB  (holds p, then weights)
    __shared__ float redm[8];
    __shared__ float reds[8];
    __shared__ __align__(16) float4 part[256];   // 4 KB
    __shared__ int   s_off[CHUNKS + 1];

    // chunk counts: parallel load + warp shfl prefix scan
    if (tid < 32) {
        int v = (tid < CHUNKS) ? g_colcnt[j * CHUNKS + tid] : 0;
        #pragma unroll
        for (int d = 1; d < 32; d <<= 1) {
            int t = __shfl_up_sync(0xffffffffu, v, d);
            if (tid >= d) v += t;
        }
        if (tid < CHUNKS) s_off[tid + 1] = v;
        if (tid == 0) s_off[0] = 0;
    }
    __syncthreads();
    int c = s_off[CHUNKS];

    // copy the 16 ordered chunk segments (2 chunks per warp, in parallel)
    for (int ch = w; ch < CHUNKS; ch += 8) {
        int beg = s_off[ch];
        int cnt = s_off[ch + 1] - beg;
        const int* src = g_colidx + (size_t)j * N1 + (size_t)ch * CHROWS;
        for (int k = lane; k < cnt; k += 32)
            sidx[beg + k] = src[k];
    }
    __syncthreads();

    float snj = g_sn[j];
    float4 acc = make_float4(0.f, 0.f, 0.f, 0.f);

    if (c == 0) {
        // all masked: softmax over constant -> uniform over N1
        for (int i = s; i < N1; i += 4) {
            const float4 v = *(const float4*)(g_edge4 + (size_t)i * 256 + (g << 2));
            acc.x += v.x; acc.y += v.y; acc.z += v.z; acc.w += v.w;
        }
        acc.x *= (1.0f / N1); acc.y *= (1.0f / N1);
        acc.z *= (1.0f / N1); acc.w *= (1.0f / N1);
    } else {
        // pass 1: compute p once (stored to smem) + online (max,sum)
        float m = -INFINITY, sm = 0.0f;
        for (int k = tid; k < c; k += 256) {
            float p = g_se[sidx[k]] + snj;
            p = p > 0.0f ? p : ALPHA * p;
            sw[k] = p;
            if (p > m) { sm = sm * expf(m - p) + 1.0f; m = p; }
            else       { sm += expf(p - m); }
        }
        // warp shfl reduction of (m, sm)
        #pragma unroll
        for (int off = 16; off; off >>= 1) {
            float m2 = __shfl_down_sync(0xffffffffu, m,  off);
            float s2 = __shfl_down_sync(0xffffffffu, sm, off);
            float mm = fmaxf(m, m2);
            float ss = 0.0f;
            if (sm > 0.0f) ss += sm * expf(m  - mm);
            if (s2 > 0.0f) ss += s2 * expf(m2 - mm);
            m = mm; sm = ss;
        }
        if (lane == 0) { redm[w] = m; reds[w] = sm; }
        __syncthreads();
        if (tid == 0) {
            float M = redm[0], S = reds[0];
            #pragma unroll
            for (int ww = 1; ww < 8; ww++) {
                float m2 = redm[ww], s2 = reds[ww];
                float mm = fmaxf(M, m2);
                float ss = 0.0f;
                if (S  > 0.0f) ss += S  * expf(M  - mm);
                if (s2 > 0.0f) ss += s2 * expf(m2 - mm);
                M = mm; S = ss;
            }
            redm[0] = M; reds[0] = 1.0f / S;
        }
        __syncthreads();
        float M    = redm[0];
        float invS = reds[0];

        // weights in-place from stored p (no second g_se gather)
        for (int k = tid; k < c; k += 256)
            sw[k] = expf(sw[k] - M) * invS;
        __syncthreads();

        // weighted gather: 4-way neighbor split x float4 columns, MLP-8
        int k = s;
        for (; k + 28 < c; k += 32) {
            float  wgt[8];
            float4 v[8];
            #pragma unroll
            for (int q = 0; q < 8; q++) {
                int kk = k + 4 * q;
                wgt[q] = sw[kk];
                v[q] = *(const float4*)(g_edge4 + (size_t)sidx[kk] * 256 + (g << 2));
            }
            #pragma unroll
            for (int q = 0; q < 8; q++) {
                acc.x += wgt[q] * v[q].x;
                acc.y += wgt[q] * v[q].y;
                acc.z += wgt[q] * v[q].z;
                acc.w += wgt[q] * v[q].w;
            }
        }
        for (; k < c; k += 4) {
            float wk = sw[k];
            const float4 v = *(const float4*)(g_edge4 + (size_t)sidx[k] * 256 + (g << 2));
            acc.x += wk * v.x; acc.y += wk * v.y; acc.z += wk * v.z; acc.w += wk * v.w;
        }
    }

    part[tid] = acc;
    __syncthreads();

    if (s == 0) {
        float4 a0 = part[g], a1 = part[64 + g], a2 = part[128 + g], a3 = part[192 + g];
        float4 o;
        o.x = a0.x + a1.x + a2.x + a3.x;
        o.y = a0.y + a1.y + a2.y + a3.y;
        o.z = a0.z + a1.z + a2.z + a3.z;
        o.w = a0.w + a1.w + a2.w + a3.w;
        o.x = o.x > 0.0f ? o.x : ALPHA * o.x;
        o.y = o.y > 0.0f ? o.y : ALPHA * o.y;
        o.z = o.z > 0.0f ? o.z : ALPHA * o.z;
        o.w = o.w > 0.0f ? o.w : ALPHA * o.w;
        *(float4*)(out + (size_t)j * 256 + (g << 2)) = o;
    }
}

// ---------------------------------------------------------------------------
extern "C" void kernel_launch(void* const* d_in, const int* in_sizes, int n_in,
                              void* d_out, int out_size)
{
    const float* x    = (const float*)d_in[0];   // [N2, 256]
    const float* adj  = (const float*)d_in[1];   // [N1, N2]
    const float* Wv2e = (const float*)d_in[2];   // [256, 256]
    const float* We2v = (const float*)d_in[3];   // [256, 256]
    const float* a    = (const float*)d_in[4];   // [1, 512]
    float* out = (float*)d_out;                  // [N2, 256]

    void *px4, *pedge, *pedge4, *psn, *pse, *prc, *pri;
    cudaGetSymbolAddress(&px4,   g_x4att);
    cudaGetSymbolAddress(&pedge, g_edge);
    cudaGetSymbolAddress(&pedge4,g_edge4);
    cudaGetSymbolAddress(&psn,   g_sn);
    cudaGetSymbolAddress(&pse,   g_se);
    cudaGetSymbolAddress(&prc,   g_rowcnt);
    cudaGetSymbolAddress(&pri,   g_rowidx);

    // 1) x_4att = x @ W_v2e
    sgemm256<<<dim3(256 / 64, N2 / 64), 256>>>(x, Wv2e, (float*)px4);

    // 2) sparsity extraction: row lists + direct column lists (no transpose)
    scan_rows4<<<N1, 256>>>(adj, N2, (int*)prc, (int*)pri, MAXR);
    col_scan<<<dim3(N2 / 256, CHUNKS), 256>>>(adj);

    // 3) edge = (adj @ x_4att) / degree   (sparse gather)
    edge_gather<<<N1, 256>>>();

    // 4) edge_4att = edge @ W_e2v
    sgemm256<<<dim3(256 / 64, N1 / 64), 256>>>((const float*)pedge, We2v, (float*)pedge4);

    // 5) attention logits components
    rowdot<<<N2 / 8, 256>>>((const float*)px4,    a,       (float*)psn, N2);
    rowdot<<<N1 / 8, 256>>>((const float*)pedge4, a + 256, (float*)pse, N1);

    // 6) per-column softmax + weighted gather + final leaky_relu
    attn_out<<<N2, 256>>>(out);
}